// round 3
// baseline (speedup 1.0000x reference)
#include <cuda_runtime.h>
#include <math.h>

// ---------------- problem constants ----------------
#define BATCH 2
#define TT    2048
#define DD    2048
#define HH    16
#define DH    128
#define DKV   512
#define DQ    1024
#define DR    64
#define DQK   192            // DH + DR
#define NTOK  (BATCH*TT)     // 4096
#define BHZ   (BATCH*HH)     // 32
#define EPS   1e-6f
#define SCALE 0.072168783648703220563f   // 1/sqrt(192)

// ---------------- scratch (device globals; allocation-free) ----------------
__device__ __align__(16) float g_cQ   [(size_t)NTOK * DQ];            // 16 MB
__device__ __align__(16) float g_cKV  [(size_t)NTOK * DKV];           // 8 MB
__device__ __align__(16) float g_q    [(size_t)NTOK * HH * DQK];      // (B,T,H,192) ~100 MB
__device__ __align__(16) float g_k    [(size_t)NTOK * HH * DQK];      // (B,T,H,192) ~100 MB
__device__ __align__(16) float g_v    [(size_t)NTOK * HH * DH];       // (B,T,H*128) ~67 MB
__device__ __align__(16) float g_kR   [(size_t)NTOK * DR];            // 1 MB
__device__ __align__(16) float g_sc   [(size_t)BHZ * TT * TT];        // 512 MB
__device__ __align__(16) float g_ao   [(size_t)NTOK * HH * DH];       // 33.5 MB

// ---------------- generic batched tiled SGEMM ----------------
// C[z] (M x N) = A[z] (M x K, row-major lda) * B[z] (K x N, row-major ldb)
// base(z) = ptr + (z/zmod)*outer + (z%zmod)*inner
// head_in>0 remaps output column j -> (j/head_in)*192 + head_off + (j%head_in)
// causal!=0 limits K to (blockIdx.y+1)*64
#define BM 64
#define BN 64
#define BKT 16

__global__ __launch_bounds__(256)
void sgemm_kernel(const float* __restrict__ A, long Ao, long Ai,
                  const float* __restrict__ Bp, long Bo, long Bi,
                  float* __restrict__ C, long Co, long Ci,
                  int zmod, int lda, int ldb, int ldc,
                  int K, int head_in, int head_off, int causal)
{
    const int z  = blockIdx.z;
    const float* Ab = A  + (long)(z / zmod) * Ao + (long)(z % zmod) * Ai;
    const float* Bb = Bp + (long)(z / zmod) * Bo + (long)(z % zmod) * Bi;
    float*       Cb = C  + (long)(z / zmod) * Co + (long)(z % zmod) * Ci;

    const int row0 = blockIdx.y * BM;
    const int col0 = blockIdx.x * BN;
    const int Keff = causal ? min(K, (int)(blockIdx.y + 1) * BM) : K;

    __shared__ float As[BKT][BM];
    __shared__ float Bs[BKT][BN];

    const int tid = threadIdx.x;
    const int tx = tid & 15, ty = tid >> 4;
    const int arow = tid >> 2,  acol = (tid & 3) * 4;     // A tile 64x16
    const int brow = tid >> 4,  bcol = (tid & 15) * 4;    // B tile 16x64

    float acc[4][4] = {};

    for (int k0 = 0; k0 < Keff; k0 += BKT) {
        float4 av = *(const float4*)(Ab + (long)(row0 + arow) * lda + k0 + acol);
        As[acol + 0][arow] = av.x;
        As[acol + 1][arow] = av.y;
        As[acol + 2][arow] = av.z;
        As[acol + 3][arow] = av.w;
        float4 bv = *(const float4*)(Bb + (long)(k0 + brow) * ldb + col0 + bcol);
        *(float4*)&Bs[brow][bcol] = bv;
        __syncthreads();
        #pragma unroll
        for (int kk = 0; kk < BKT; kk++) {
            float4 af = *(const float4*)&As[kk][ty * 4];
            float4 bf = *(const float4*)&Bs[kk][tx * 4];
            float a0[4] = {af.x, af.y, af.z, af.w};
            float b0[4] = {bf.x, bf.y, bf.z, bf.w};
            #pragma unroll
            for (int i = 0; i < 4; i++)
                #pragma unroll
                for (int j = 0; j < 4; j++)
                    acc[i][j] = fmaf(a0[i], b0[j], acc[i][j]);
        }
        __syncthreads();
    }

    #pragma unroll
    for (int i = 0; i < 4; i++) {
        const int r = row0 + ty * 4 + i;
        #pragma unroll
        for (int j = 0; j < 4; j++) {
            int c = col0 + tx * 4 + j;
            int oc = (head_in > 0) ? (c / head_in) * DQK + head_off + (c % head_in) : c;
            Cb[(long)r * ldc + oc] = acc[i][j];
        }
    }
}

// ---------------- RMSNorm in place (one block per row) ----------------
__global__ __launch_bounds__(256)
void rmsnorm_kernel(float* __restrict__ x, const float* __restrict__ w, int len)
{
    float* p = x + (long)blockIdx.x * len;
    __shared__ float red[256];
    const int tid = threadIdx.x;
    float s = 0.f;
    for (int i = tid; i < len; i += 256) { float v = p[i]; s += v * v; }
    red[tid] = s; __syncthreads();
    for (int d = 128; d > 0; d >>= 1) { if (tid < d) red[tid] += red[tid + d]; __syncthreads(); }
    const float inv = rsqrtf(red[0] / (float)len + EPS);
    for (int i = tid; i < len; i += 256) p[i] = p[i] * inv * w[i];
}

// ---------------- RoPE on q rope slice (in place) ----------------
__global__ void rope_q_kernel(float* __restrict__ q)
{
    long idx = (long)blockIdx.x * blockDim.x + threadIdx.x;   // B*T*H*32
    if (idx >= (long)NTOK * HH * 32) return;
    const int i = idx & 31;
    const int h = (idx >> 5) & 15;
    const long tok = idx >> 9;                                 // b*T + t
    const int t = (int)(tok & (TT - 1));
    const float inv = powf(500000.0f, -(float)i / 32.0f);
    float c, s;
    sincosf((float)t * inv, &s, &c);
    float* p = q + tok * (HH * DQK) + (long)h * DQK + DH;
    const float a = p[i], b = p[i + 32];
    p[i]      = a * c - b * s;
    p[i + 32] = b * c + a * s;
}

// ---------------- RoPE on k_R + broadcast into g_k for all heads ----------------
__global__ void rope_k_kernel(const float* __restrict__ kR, float* __restrict__ k)
{
    long idx = (long)blockIdx.x * blockDim.x + threadIdx.x;   // B*T*32
    if (idx >= (long)NTOK * 32) return;
    const int i = idx & 31;
    const long tok = idx >> 5;
    const int t = (int)(tok & (TT - 1));
    const float inv = powf(500000.0f, -(float)i / 32.0f);
    float c, s;
    sincosf((float)t * inv, &s, &c);
    const float a = kR[tok * DR + i], b = kR[tok * DR + i + 32];
    const float r0 = a * c - b * s;
    const float r1 = b * c + a * s;
    float* base = k + tok * (HH * DQK) + DH;
    #pragma unroll
    for (int h = 0; h < HH; h++) {
        base[(long)h * DQK + i]      = r0;
        base[(long)h * DQK + i + 32] = r1;
    }
}

// ---------------- scores: S = Q Kt * SCALE, causal masked ----------------
__global__ __launch_bounds__(256)
void scores_kernel(const float* __restrict__ q, const float* __restrict__ k,
                   float* __restrict__ sc)
{
    const int kt = blockIdx.x, qt = blockIdx.y, z = blockIdx.z;
    if (kt > qt) return;
    const int b = z >> 4, h = z & 15;
    const float* qb = q + (long)b * TT * HH * DQK + (long)h * DQK;  // row stride 3072
    const float* kb = k + (long)b * TT * HH * DQK + (long)h * DQK;
    const int q0 = qt * 64, k0 = kt * 64;

    __shared__ float Qs[16][64];
    __shared__ float Ks[16][64];

    const int tid = threadIdx.x;
    const int tx = tid & 15, ty = tid >> 4;
    const int arow = tid >> 2, acol = (tid & 3) * 4;

    float acc[4][4] = {};
    const int RS = HH * DQK;   // 3072

    for (int d0 = 0; d0 < DQK; d0 += 16) {
        float4 qv = *(const float4*)(qb + (long)(q0 + arow) * RS + d0 + acol);
        Qs[acol + 0][arow] = qv.x; Qs[acol + 1][arow] = qv.y;
        Qs[acol + 2][arow] = qv.z; Qs[acol + 3][arow] = qv.w;
        float4 kv = *(const float4*)(kb + (long)(k0 + arow) * RS + d0 + acol);
        Ks[acol + 0][arow] = kv.x; Ks[acol + 1][arow] = kv.y;
        Ks[acol + 2][arow] = kv.z; Ks[acol + 3][arow] = kv.w;
        __syncthreads();
        #pragma unroll
        for (int kk = 0; kk < 16; kk++) {
            float4 af = *(const float4*)&Qs[kk][ty * 4];
            float4 bf = *(const float4*)&Ks[kk][tx * 4];
            float a0[4] = {af.x, af.y, af.z, af.w};
            float b0[4] = {bf.x, bf.y, bf.z, bf.w};
            #pragma unroll
            for (int i = 0; i < 4; i++)
                #pragma unroll
                for (int j = 0; j < 4; j++)
                    acc[i][j] = fmaf(a0[i], b0[j], acc[i][j]);
        }
        __syncthreads();
    }

    float* out = sc + (long)z * TT * TT;
    #pragma unroll
    for (int i = 0; i < 4; i++) {
        const int qi = q0 + ty * 4 + i;
        #pragma unroll
        for (int j = 0; j < 4; j++) {
            const int kj = k0 + tx * 4 + j;
            float v = acc[i][j] * SCALE;
            if (qt == kt && kj > qi) v = -INFINITY;
            out[(long)qi * TT + kj] = v;
        }
    }
}

// ---------------- row softmax (causal length) ----------------
__global__ __launch_bounds__(256)
void softmax_kernel(float* __restrict__ sc)
{
    const int qpos = blockIdx.x, z = blockIdx.y;
    float* row = sc + ((long)z * TT + qpos) * TT;
    const int kend = ((qpos >> 6) + 1) << 6;      // tile-padded; masked = -inf -> exp 0
    __shared__ float buf[2048];
    __shared__ float red[256];
    const int tid = threadIdx.x;

    float m = -INFINITY;
    for (int i = tid; i < kend; i += 256) m = fmaxf(m, row[i]);
    red[tid] = m; __syncthreads();
    for (int d = 128; d > 0; d >>= 1) { if (tid < d) red[tid] = fmaxf(red[tid], red[tid + d]); __syncthreads(); }
    m = red[0]; __syncthreads();

    float s = 0.f;
    for (int i = tid; i < kend; i += 256) { float e = expf(row[i] - m); buf[i] = e; s += e; }
    red[tid] = s; __syncthreads();
    for (int d = 128; d > 0; d >>= 1) { if (tid < d) red[tid] += red[tid + d]; __syncthreads(); }
    const float inv = 1.0f / red[0];
    for (int i = tid; i < kend; i += 256) row[i] = buf[i] * inv;
}

// ---------------- launch ----------------
extern "C" void kernel_launch(void* const* d_in, const int* in_sizes, int n_in,
                              void* d_out, int out_size)
{
    const float* x     = (const float*)d_in[0];
    const float* W_DQ  = (const float*)d_in[1];
    const float* W_UQ  = (const float*)d_in[2];
    const float* W_QR  = (const float*)d_in[3];
    const float* W_DKV = (const float*)d_in[4];
    const float* W_UK  = (const float*)d_in[5];
    const float* W_UV  = (const float*)d_in[6];
    const float* W_KR  = (const float*)d_in[7];
    const float* W_O   = (const float*)d_in[8];
    const float* qnw   = (const float*)d_in[9];
    const float* kvnw  = (const float*)d_in[10];
    float* out = (float*)d_out;

    float *cQ, *cKV, *q, *k, *v, *kR, *sc, *ao;
    cudaGetSymbolAddress((void**)&cQ,  g_cQ);
    cudaGetSymbolAddress((void**)&cKV, g_cKV);
    cudaGetSymbolAddress((void**)&q,   g_q);
    cudaGetSymbolAddress((void**)&k,   g_k);
    cudaGetSymbolAddress((void**)&v,   g_v);
    cudaGetSymbolAddress((void**)&kR,  g_kR);
    cudaGetSymbolAddress((void**)&sc,  g_sc);
    cudaGetSymbolAddress((void**)&ao,  g_ao);

    const dim3 blk(256);

    // 1) c_Q = x @ W_DQ ; RMSNorm
    sgemm_kernel<<<dim3(DQ/64, NTOK/64, 1), blk>>>(x,0,0, W_DQ,0,0, cQ,0,0,
        1, DD, DQ, DQ, DD, 0,0,0);
    rmsnorm_kernel<<<NTOK, blk>>>(cQ, qnw, DQ);

    // 2) c_KV = x @ W_DKV ; RMSNorm
    sgemm_kernel<<<dim3(DKV/64, NTOK/64, 1), blk>>>(x,0,0, W_DKV,0,0, cKV,0,0,
        1, DD, DKV, DKV, DD, 0,0,0);
    rmsnorm_kernel<<<NTOK, blk>>>(cKV, kvnw, DKV);

    // 3) q content + rope parts into g_q (B,T,H,192)
    sgemm_kernel<<<dim3((HH*DH)/64, NTOK/64, 1), blk>>>(cQ,0,0, W_UQ,0,0, q,0,0,
        1, DQ, HH*DH, HH*DQK, DQ, DH, 0, 0);
    sgemm_kernel<<<dim3((HH*DR)/64, NTOK/64, 1), blk>>>(cQ,0,0, W_QR,0,0, q,0,0,
        1, DQ, HH*DR, HH*DQK, DQ, DR, DH, 0);

    // 4) k content into g_k ; v into g_v (plain B,T,H*128)
    sgemm_kernel<<<dim3((HH*DH)/64, NTOK/64, 1), blk>>>(cKV,0,0, W_UK,0,0, k,0,0,
        1, DKV, HH*DH, HH*DQK, DKV, DH, 0, 0);
    sgemm_kernel<<<dim3((HH*DH)/64, NTOK/64, 1), blk>>>(cKV,0,0, W_UV,0,0, v,0,0,
        1, DKV, HH*DH, HH*DH, DKV, 0, 0, 0);

    // 5) k_R = x @ W_KR
    sgemm_kernel<<<dim3(DR/64, NTOK/64, 1), blk>>>(x,0,0, W_KR,0,0, kR,0,0,
        1, DD, DR, DR, DD, 0,0,0);

    // 6) RoPE
    rope_q_kernel<<<((long)NTOK*HH*32 + 255)/256, blk>>>(q);
    rope_k_kernel<<<((long)NTOK*32 + 255)/256, blk>>>(kR, k);

    // 7) attention: scores -> softmax -> PV
    scores_kernel<<<dim3(TT/64, TT/64, BHZ), blk>>>(q, k, sc);
    softmax_kernel<<<dim3(TT, BHZ), blk>>>(sc);

    // PV: per z=(b*16+h): O[T,128] = P[T,Tcausal] @ V_bh[T,128]
    sgemm_kernel<<<dim3(DH/64, TT/64, BHZ), blk>>>(
        sc, (long)HH*TT*TT, (long)TT*TT,
        v,  (long)TT*HH*DH, (long)DH,
        ao, (long)TT*HH*DH, (long)DH,
        HH, TT, HH*DH, HH*DH,
        TT, 0, 0, 1);

    // 8) final: out = ao @ W_O
    sgemm_kernel<<<dim3(DD/64, NTOK/64, 1), blk>>>(ao,0,0, W_O,0,0, out,0,0,
        1, HH*DH, DD, DD, HH*DH, 0,0,0);
}

// round 5
// speedup vs baseline: 1.1686x; 1.1686x over previous
#include <cuda_runtime.h>
#include <math.h>

// ---------------- problem constants ----------------
#define BATCH 2
#define TT    2048
#define DD    2048
#define HH    16
#define DH    128
#define DKV   512
#define DQ    1024
#define DR    64
#define DQK   192            // DH + DR
#define NTOK  (BATCH*TT)     // 4096
#define BHZ   (BATCH*HH)     // 32
#define EPS   1e-6f
#define SCALE 0.072168783648703220563f   // 1/sqrt(192)

// ---------------- scratch (device globals; allocation-free) ----------------
__device__ __align__(16) float g_cQ   [(size_t)NTOK * DQ];
__device__ __align__(16) float g_cKV  [(size_t)NTOK * DKV];
__device__ __align__(16) float g_q    [(size_t)NTOK * HH * DQK];
__device__ __align__(16) float g_k    [(size_t)NTOK * HH * DQK];
__device__ __align__(16) float g_v    [(size_t)NTOK * HH * DH];
__device__ __align__(16) float g_kR   [(size_t)NTOK * DR];
__device__ __align__(16) float g_sc   [(size_t)BHZ * TT * TT];
__device__ __align__(16) float g_ao   [(size_t)NTOK * HH * DH];

// =====================================================================
// 128x128x16 SGEMM, 8x8 micro-tile (4+4 split), 256 threads
// C[z] (M x N) = A[z] (M x K) * B[z] (K x N), all row-major
// base(z) = ptr + (z/zmod)*outer + (z%zmod)*inner
// head_in>0 remaps out column j -> (j/head_in)*DQK + head_off + (j%head_in)
// causal!=0 limits K to (blockIdx.y+1)*128
// =====================================================================
#define TM 128
#define TN 128
#define TKS 16

__global__ __launch_bounds__(256)
void sgemm128_kernel(const float* __restrict__ A, long Ao, long Ai,
                     const float* __restrict__ Bp, long Bo, long Bi,
                     float* __restrict__ C, long Co, long Ci,
                     int zmod, int lda, int ldb, int ldc,
                     int K, int head_in, int head_off, int causal)
{
    const int z  = blockIdx.z;
    const float* Ab = A  + (long)(z / zmod) * Ao + (long)(z % zmod) * Ai;
    const float* Bb = Bp + (long)(z / zmod) * Bo + (long)(z % zmod) * Bi;
    float*       Cb = C  + (long)(z / zmod) * Co + (long)(z % zmod) * Ci;

    const int row0 = blockIdx.y * TM;
    const int col0 = blockIdx.x * TN;
    const int Keff = causal ? min(K, (int)(blockIdx.y + 1) * TM) : K;

    __shared__ float As[TKS][TM];
    __shared__ float Bs[TKS][TN];

    const int tid = threadIdx.x;
    const int ty = tid >> 4, tx = tid & 15;

    float acc[8][8] = {};

    for (int k0 = 0; k0 < Keff; k0 += TKS) {
        // load A tile 128x16 (2 float4 / thread), store transposed
        #pragma unroll
        for (int m = 0; m < 2; m++) {
            const int f = tid * 2 + m;          // 0..511
            const int r = f >> 2;               // 0..127
            const int c = (f & 3) * 4;          // 0,4,8,12
            float4 av = *(const float4*)(Ab + (long)(row0 + r) * lda + k0 + c);
            As[c + 0][r] = av.x;
            As[c + 1][r] = av.y;
            As[c + 2][r] = av.z;
            As[c + 3][r] = av.w;
        }
        // load B tile 16x128 (2 float4 / thread), direct
        #pragma unroll
        for (int m = 0; m < 2; m++) {
            const int f = tid * 2 + m;          // 0..511
            const int r = f >> 5;               // 0..15
            const int c = (f & 31) * 4;         // 0..124
            *(float4*)&Bs[r][c] =
                *(const float4*)(Bb + (long)(k0 + r) * ldb + col0 + c);
        }
        __syncthreads();

        #pragma unroll
        for (int kk = 0; kk < TKS; kk++) {
            float a[8], b[8];
            *(float4*)(a + 0) = *(const float4*)&As[kk][ty * 4];
            *(float4*)(a + 4) = *(const float4*)&As[kk][64 + ty * 4];
            *(float4*)(b + 0) = *(const float4*)&Bs[kk][tx * 4];
            *(float4*)(b + 4) = *(const float4*)&Bs[kk][64 + tx * 4];
            #pragma unroll
            for (int i = 0; i < 8; i++)
                #pragma unroll
                for (int j = 0; j < 8; j++)
                    acc[i][j] = fmaf(a[i], b[j], acc[i][j]);
        }
        __syncthreads();
    }

    #pragma unroll
    for (int i = 0; i < 8; i++) {
        const int r = row0 + ((i < 4) ? (ty * 4 + i) : (64 + ty * 4 + i - 4));
        #pragma unroll
        for (int j = 0; j < 8; j++) {
            const int c = col0 + ((j < 4) ? (tx * 4 + j) : (64 + tx * 4 + j - 4));
            const int oc = (head_in > 0)
                ? (c / head_in) * DQK + head_off + (c % head_in) : c;
            Cb[(long)r * ldc + oc] = acc[i][j];
        }
    }
}

// =====================================================================
// scores: S = Q Kt * SCALE, causal masked (128x128 tiles)
// q,k layout (B,T,H,192), row stride 3072
// =====================================================================
__global__ __launch_bounds__(256)
void scores128_kernel(const float* __restrict__ q, const float* __restrict__ k,
                      float* __restrict__ sc)
{
    const int kt = blockIdx.x, qt = blockIdx.y, z = blockIdx.z;
    if (kt > qt) return;
    const int b = z >> 4, h = z & 15;
    const float* qb = q + (long)b * TT * HH * DQK + (long)h * DQK;
    const float* kb = k + (long)b * TT * HH * DQK + (long)h * DQK;
    const int q0 = qt * TM, k0 = kt * TN;
    const int RS = HH * DQK;   // 3072

    __shared__ float Qs[TKS][TM];
    __shared__ float Ks[TKS][TN];

    const int tid = threadIdx.x;
    const int ty = tid >> 4, tx = tid & 15;

    float acc[8][8] = {};

    for (int d0 = 0; d0 < DQK; d0 += TKS) {
        #pragma unroll
        for (int m = 0; m < 2; m++) {
            const int f = tid * 2 + m;
            const int r = f >> 2;
            const int c = (f & 3) * 4;
            float4 qv = *(const float4*)(qb + (long)(q0 + r) * RS + d0 + c);
            Qs[c + 0][r] = qv.x; Qs[c + 1][r] = qv.y;
            Qs[c + 2][r] = qv.z; Qs[c + 3][r] = qv.w;
            float4 kv = *(const float4*)(kb + (long)(k0 + r) * RS + d0 + c);
            Ks[c + 0][r] = kv.x; Ks[c + 1][r] = kv.y;
            Ks[c + 2][r] = kv.z; Ks[c + 3][r] = kv.w;
        }
        __syncthreads();
        #pragma unroll
        for (int kk = 0; kk < TKS; kk++) {
            float a[8], b2[8];
            *(float4*)(a + 0)  = *(const float4*)&Qs[kk][ty * 4];
            *(float4*)(a + 4)  = *(const float4*)&Qs[kk][64 + ty * 4];
            *(float4*)(b2 + 0) = *(const float4*)&Ks[kk][tx * 4];
            *(float4*)(b2 + 4) = *(const float4*)&Ks[kk][64 + tx * 4];
            #pragma unroll
            for (int i = 0; i < 8; i++)
                #pragma unroll
                for (int j = 0; j < 8; j++)
                    acc[i][j] = fmaf(a[i], b2[j], acc[i][j]);
        }
        __syncthreads();
    }

    float* out = sc + (long)z * TT * TT;
    #pragma unroll
    for (int i = 0; i < 8; i++) {
        const int qi = q0 + ((i < 4) ? (ty * 4 + i) : (64 + ty * 4 + i - 4));
        #pragma unroll
        for (int j = 0; j < 8; j++) {
            const int kj = k0 + ((j < 4) ? (tx * 4 + j) : (64 + tx * 4 + j - 4));
            float v = acc[i][j] * SCALE;
            if (qt == kt && kj > qi) v = -INFINITY;
            out[(long)qi * TT + kj] = v;
        }
    }
}

// ---------------- 64x64 SGEMM (kept for N=64 case: W_KR) ----------------
#define BM 64
#define BN 64
#define BKT 16

__global__ __launch_bounds__(256)
void sgemm_kernel(const float* __restrict__ A, long Ao, long Ai,
                  const float* __restrict__ Bp, long Bo, long Bi,
                  float* __restrict__ C, long Co, long Ci,
                  int zmod, int lda, int ldb, int ldc,
                  int K, int head_in, int head_off, int causal)
{
    const int z  = blockIdx.z;
    const float* Ab = A  + (long)(z / zmod) * Ao + (long)(z % zmod) * Ai;
    const float* Bb = Bp + (long)(z / zmod) * Bo + (long)(z % zmod) * Bi;
    float*       Cb = C  + (long)(z / zmod) * Co + (long)(z % zmod) * Ci;

    const int row0 = blockIdx.y * BM;
    const int col0 = blockIdx.x * BN;
    const int Keff = causal ? min(K, (int)(blockIdx.y + 1) * BM) : K;

    __shared__ float As[BKT][BM];
    __shared__ float Bs[BKT][BN];

    const int tid = threadIdx.x;
    const int tx = tid & 15, ty = tid >> 4;
    const int arow = tid >> 2,  acol = (tid & 3) * 4;
    const int brow = tid >> 4,  bcol = (tid & 15) * 4;

    float acc[4][4] = {};

    for (int k0 = 0; k0 < Keff; k0 += BKT) {
        float4 av = *(const float4*)(Ab + (long)(row0 + arow) * lda + k0 + acol);
        As[acol + 0][arow] = av.x;
        As[acol + 1][arow] = av.y;
        As[acol + 2][arow] = av.z;
        As[acol + 3][arow] = av.w;
        float4 bv = *(const float4*)(Bb + (long)(k0 + brow) * ldb + col0 + bcol);
        *(float4*)&Bs[brow][bcol] = bv;
        __syncthreads();
        #pragma unroll
        for (int kk = 0; kk < BKT; kk++) {
            float4 af = *(const float4*)&As[kk][ty * 4];
            float4 bf = *(const float4*)&Bs[kk][tx * 4];
            float a0[4] = {af.x, af.y, af.z, af.w};
            float b0[4] = {bf.x, bf.y, bf.z, bf.w};
            #pragma unroll
            for (int i = 0; i < 4; i++)
                #pragma unroll
                for (int j = 0; j < 4; j++)
                    acc[i][j] = fmaf(a0[i], b0[j], acc[i][j]);
        }
        __syncthreads();
    }

    #pragma unroll
    for (int i = 0; i < 4; i++) {
        const int r = row0 + ty * 4 + i;
        #pragma unroll
        for (int j = 0; j < 4; j++) {
            int c = col0 + tx * 4 + j;
            int oc = (head_in > 0) ? (c / head_in) * DQK + head_off + (c % head_in) : c;
            Cb[(long)r * ldc + oc] = acc[i][j];
        }
    }
}

// ---------------- RMSNorm in place (one block per row) ----------------
__global__ __launch_bounds__(256)
void rmsnorm_kernel(float* __restrict__ x, const float* __restrict__ w, int len)
{
    float* p = x + (long)blockIdx.x * len;
    __shared__ float red[256];
    const int tid = threadIdx.x;
    float s = 0.f;
    for (int i = tid; i < len; i += 256) { float v = p[i]; s += v * v; }
    red[tid] = s; __syncthreads();
    for (int d = 128; d > 0; d >>= 1) { if (tid < d) red[tid] += red[tid + d]; __syncthreads(); }
    const float inv = rsqrtf(red[0] / (float)len + EPS);
    for (int i = tid; i < len; i += 256) p[i] = p[i] * inv * w[i];
}

// ---------------- RoPE on q rope slice (in place) ----------------
__global__ void rope_q_kernel(float* __restrict__ q)
{
    long idx = (long)blockIdx.x * blockDim.x + threadIdx.x;   // B*T*H*32
    if (idx >= (long)NTOK * HH * 32) return;
    const int i = idx & 31;
    const int h = (idx >> 5) & 15;
    const long tok = idx >> 9;
    const int t = (int)(tok & (TT - 1));
    const float inv = powf(500000.0f, -(float)i / 32.0f);
    float c, s;
    sincosf((float)t * inv, &s, &c);
    float* p = q + tok * (HH * DQK) + (long)h * DQK + DH;
    const float a = p[i], b = p[i + 32];
    p[i]      = a * c - b * s;
    p[i + 32] = b * c + a * s;
}

// ---------------- RoPE on k_R + broadcast into g_k for all heads ----------------
__global__ void rope_k_kernel(const float* __restrict__ kR, float* __restrict__ k)
{
    long idx = (long)blockIdx.x * blockDim.x + threadIdx.x;   // B*T*32
    if (idx >= (long)NTOK * 32) return;
    const int i = idx & 31;
    const long tok = idx >> 5;
    const int t = (int)(tok & (TT - 1));
    const float inv = powf(500000.0f, -(float)i / 32.0f);
    float c, s;
    sincosf((float)t * inv, &s, &c);
    const float a = kR[tok * DR + i], b = kR[tok * DR + i + 32];
    const float r0 = a * c - b * s;
    const float r1 = b * c + a * s;
    float* base = k + tok * (HH * DQK) + DH;
    #pragma unroll
    for (int h = 0; h < HH; h++) {
        base[(long)h * DQK + i]      = r0;
        base[(long)h * DQK + i + 32] = r1;
    }
}

// ---------------- row softmax (causal length, 128-tile granularity) ----------------
__global__ __launch_bounds__(256)
void softmax_kernel(float* __restrict__ sc)
{
    const int qpos = blockIdx.x, z = blockIdx.y;
    float* row = sc + ((long)z * TT + qpos) * TT;
    const int kend = ((qpos >> 7) + 1) << 7;      // 128-tile padded; masked -inf -> 0
    __shared__ float buf[2048];
    __shared__ float red[256];
    const int tid = threadIdx.x;

    float m = -INFINITY;
    for (int i = tid; i < kend; i += 256) m = fmaxf(m, row[i]);
    red[tid] = m; __syncthreads();
    for (int d = 128; d > 0; d >>= 1) { if (tid < d) red[tid] = fmaxf(red[tid], red[tid + d]); __syncthreads(); }
    m = red[0]; __syncthreads();

    float s = 0.f;
    for (int i = tid; i < kend; i += 256) { float e = expf(row[i] - m); buf[i] = e; s += e; }
    red[tid] = s; __syncthreads();
    for (int d = 128; d > 0; d >>= 1) { if (tid < d) red[tid] += red[tid + d]; __syncthreads(); }
    const float inv = 1.0f / red[0];
    for (int i = tid; i < kend; i += 256) row[i] = buf[i] * inv;
}

// ---------------- launch ----------------
extern "C" void kernel_launch(void* const* d_in, const int* in_sizes, int n_in,
                              void* d_out, int out_size)
{
    const float* x     = (const float*)d_in[0];
    const float* W_DQ  = (const float*)d_in[1];
    const float* W_UQ  = (const float*)d_in[2];
    const float* W_QR  = (const float*)d_in[3];
    const float* W_DKV = (const float*)d_in[4];
    const float* W_UK  = (const float*)d_in[5];
    const float* W_UV  = (const float*)d_in[6];
    const float* W_KR  = (const float*)d_in[7];
    const float* W_O   = (const float*)d_in[8];
    const float* qnw   = (const float*)d_in[9];
    const float* kvnw  = (const float*)d_in[10];
    float* out = (float*)d_out;

    float *cQ, *cKV, *q, *k, *v, *kR, *sc, *ao;
    cudaGetSymbolAddress((void**)&cQ,  g_cQ);
    cudaGetSymbolAddress((void**)&cKV, g_cKV);
    cudaGetSymbolAddress((void**)&q,   g_q);
    cudaGetSymbolAddress((void**)&k,   g_k);
    cudaGetSymbolAddress((void**)&v,   g_v);
    cudaGetSymbolAddress((void**)&kR,  g_kR);
    cudaGetSymbolAddress((void**)&sc,  g_sc);
    cudaGetSymbolAddress((void**)&ao,  g_ao);

    const dim3 blk(256);

    // 1) c_Q = x @ W_DQ ; RMSNorm
    sgemm128_kernel<<<dim3(DQ/128, NTOK/128, 1), blk>>>(x,0,0, W_DQ,0,0, cQ,0,0,
        1, DD, DQ, DQ, DD, 0,0,0);
    rmsnorm_kernel<<<NTOK, blk>>>(cQ, qnw, DQ);

    // 2) c_KV = x @ W_DKV ; RMSNorm
    sgemm128_kernel<<<dim3(DKV/128, NTOK/128, 1), blk>>>(x,0,0, W_DKV,0,0, cKV,0,0,
        1, DD, DKV, DKV, DD, 0,0,0);
    rmsnorm_kernel<<<NTOK, blk>>>(cKV, kvnw, DKV);

    // 3) q content + rope parts into g_q (B,T,H,192)
    sgemm128_kernel<<<dim3((HH*DH)/128, NTOK/128, 1), blk>>>(cQ,0,0, W_UQ,0,0, q,0,0,
        1, DQ, HH*DH, HH*DQK, DQ, DH, 0, 0);
    sgemm128_kernel<<<dim3((HH*DR)/128, NTOK/128, 1), blk>>>(cQ,0,0, W_QR,0,0, q,0,0,
        1, DQ, HH*DR, HH*DQK, DQ, DR, DH, 0);

    // 4) k content into g_k ; v into g_v (plain B,T,H*128)
    sgemm128_kernel<<<dim3((HH*DH)/128, NTOK/128, 1), blk>>>(cKV,0,0, W_UK,0,0, k,0,0,
        1, DKV, HH*DH, HH*DQK, DKV, DH, 0, 0);
    sgemm128_kernel<<<dim3((HH*DH)/128, NTOK/128, 1), blk>>>(cKV,0,0, W_UV,0,0, v,0,0,
        1, DKV, HH*DH, HH*DH, DKV, 0, 0, 0);

    // 5) k_R = x @ W_KR  (N=64 -> 64-wide kernel)
    sgemm_kernel<<<dim3(DR/64, NTOK/64, 1), blk>>>(x,0,0, W_KR,0,0, kR,0,0,
        1, DD, DR, DR, DD, 0,0,0);

    // 6) RoPE
    rope_q_kernel<<<((long)NTOK*HH*32 + 255)/256, blk>>>(q);
    rope_k_kernel<<<((long)NTOK*32 + 255)/256, blk>>>(kR, k);

    // 7) attention: scores -> softmax -> PV
    scores128_kernel<<<dim3(TT/128, TT/128, BHZ), blk>>>(q, k, sc);
    softmax_kernel<<<dim3(TT, BHZ), blk>>>(sc);

    // PV: per z=(b*16+h): O[T,128] = P[T,Tcausal] @ V_bh[T,128]
    sgemm128_kernel<<<dim3(DH/128, TT/128, BHZ), blk>>>(
        sc, (long)HH*TT*TT, (long)TT*TT,
        v,  (long)TT*HH*DH, (long)DH,
        ao, (long)TT*HH*DH, (long)DH,
        HH, TT, HH*DH, HH*DH,
        TT, 0, 0, 1);

    // 8) final: out = ao @ W_O
    sgemm128_kernel<<<dim3(DD/128, NTOK/128, 1), blk>>>(ao,0,0, W_O,0,0, out,0,0,
        1, HH*DH, DD, DD, HH*DH, 0,0,0);
}

// round 7
// speedup vs baseline: 1.8329x; 1.5684x over previous
#include <cuda_runtime.h>
#include <cuda_bf16.h>
#include <cstdint>
#include <math.h>

// ---------------- problem constants ----------------
#define BATCH 2
#define TT    2048
#define DD    2048
#define HH    16
#define DH    128
#define DKV   512
#define DQ    1024
#define DR    64
#define DQK   192            // DH + DR
#define NTOK  (BATCH*TT)     // 4096
#define BHZ   (BATCH*HH)     // 32
#define EPS   1e-6f
#define SCALE 0.072168783648703220563f   // 1/sqrt(192)

// ---------------- scratch (device globals; allocation-free) ----------------
__device__ __align__(16) float g_cQ   [(size_t)NTOK * DQ];
__device__ __align__(16) float g_cKV  [(size_t)NTOK * DKV];
__device__ __align__(16) float g_q    [(size_t)NTOK * HH * DQK];
__device__ __align__(16) float g_k    [(size_t)NTOK * HH * DQK];
__device__ __align__(16) float g_v    [(size_t)NTOK * HH * DH];
__device__ __align__(16) float g_kR   [(size_t)NTOK * DR];
__device__ __align__(16) float g_sc   [(size_t)BHZ * TT * TT];
__device__ __align__(16) float g_ao   [(size_t)NTOK * HH * DH];

// =====================================================================
// Tensor-core GEMM with fp32 accuracy via bf16 hi/lo split.
// C (M x N) = A (M x K) * B (K x N), row-major, single batch.
// C = Ah*Bh + Ah*Bl + Al*Bh  (lo*lo dropped, ~2^-18 relative)
// Block tile 128x128, K-step 32, 256 threads = 8 warps (2x4),
// warp tile 64x32, mma.sync m16n8k16 bf16.
// head_in>0 remaps out column j -> (j/head_in)*DQK + head_off + (j%head_in)
// =====================================================================
#define ASTR 40     // smem A row stride in bf16 (80B: 16B-aligned rows)
#define BSTR 136    // smem B row stride in bf16 (272B: 16B-aligned rows)

__device__ __forceinline__ unsigned smem_u32(const void* p) {
    return (unsigned)__cvta_generic_to_shared(p);
}
__device__ __forceinline__ void ldsm4(unsigned& r0, unsigned& r1,
                                      unsigned& r2, unsigned& r3, unsigned a) {
    asm volatile("ldmatrix.sync.aligned.m8n8.x4.shared.b16 {%0,%1,%2,%3}, [%4];"
                 : "=r"(r0), "=r"(r1), "=r"(r2), "=r"(r3) : "r"(a));
}
__device__ __forceinline__ void ldsm4t(unsigned& r0, unsigned& r1,
                                       unsigned& r2, unsigned& r3, unsigned a) {
    asm volatile("ldmatrix.sync.aligned.m8n8.x4.trans.shared.b16 {%0,%1,%2,%3}, [%4];"
                 : "=r"(r0), "=r"(r1), "=r"(r2), "=r"(r3) : "r"(a));
}
__device__ __forceinline__ void mma16816(float* d, const unsigned* a, const unsigned* b) {
    asm volatile("mma.sync.aligned.m16n8k16.row.col.f32.bf16.bf16.f32 "
                 "{%0,%1,%2,%3}, {%4,%5,%6,%7}, {%8,%9}, {%0,%1,%2,%3};"
                 : "+f"(d[0]), "+f"(d[1]), "+f"(d[2]), "+f"(d[3])
                 : "r"(a[0]), "r"(a[1]), "r"(a[2]), "r"(a[3]),
                   "r"(b[0]), "r"(b[1]));
}
__device__ __forceinline__ void split_store(__nv_bfloat16* hi, __nv_bfloat16* lo, float v) {
    __nv_bfloat16 h = __float2bfloat16(v);
    *hi = h;
    *lo = __float2bfloat16(v - __bfloat162float(h));
}

__global__ __launch_bounds__(256)
void bgemm_kernel(const float* __restrict__ A, const float* __restrict__ B,
                  float* __restrict__ C, int lda, int ldb, int ldc,
                  int K, int head_in, int head_off)
{
    __shared__ __align__(16) __nv_bfloat16 sAh[128 * ASTR];
    __shared__ __align__(16) __nv_bfloat16 sAl[128 * ASTR];
    __shared__ __align__(16) __nv_bfloat16 sBh[32 * BSTR];
    __shared__ __align__(16) __nv_bfloat16 sBl[32 * BSTR];

    const int tid = threadIdx.x;
    const int wid = tid >> 5, lane = tid & 31;
    const int wm = (wid & 1) * 64;      // warp row offset in tile
    const int wn = (wid >> 1) * 32;     // warp col offset in tile
    const int row0 = blockIdx.y * 128;
    const int col0 = blockIdx.x * 128;

    float acc[4][4][4];
    #pragma unroll
    for (int i = 0; i < 4; i++)
        #pragma unroll
        for (int j = 0; j < 4; j++)
            #pragma unroll
            for (int r = 0; r < 4; r++) acc[i][j][r] = 0.f;

    for (int k0 = 0; k0 < K; k0 += 32) {
        // A tile 128x32 fp32 -> hi/lo bf16
        #pragma unroll
        for (int m = 0; m < 4; m++) {
            const int f = tid + m * 256;        // 0..1023
            const int r = f >> 3;               // 0..127
            const int c = (f & 7) * 4;          // 0..28
            float4 v = *(const float4*)(A + (long)(row0 + r) * lda + k0 + c);
            split_store(&sAh[r * ASTR + c + 0], &sAl[r * ASTR + c + 0], v.x);
            split_store(&sAh[r * ASTR + c + 1], &sAl[r * ASTR + c + 1], v.y);
            split_store(&sAh[r * ASTR + c + 2], &sAl[r * ASTR + c + 2], v.z);
            split_store(&sAh[r * ASTR + c + 3], &sAl[r * ASTR + c + 3], v.w);
        }
        // B tile 32x128 fp32 -> hi/lo bf16
        #pragma unroll
        for (int m = 0; m < 4; m++) {
            const int f = tid + m * 256;
            const int r = f >> 5;               // 0..31
            const int c = (f & 31) * 4;         // 0..124
            float4 v = *(const float4*)(B + (long)(k0 + r) * ldb + col0 + c);
            split_store(&sBh[r * BSTR + c + 0], &sBl[r * BSTR + c + 0], v.x);
            split_store(&sBh[r * BSTR + c + 1], &sBl[r * BSTR + c + 1], v.y);
            split_store(&sBh[r * BSTR + c + 2], &sBl[r * BSTR + c + 2], v.z);
            split_store(&sBh[r * BSTR + c + 3], &sBl[r * BSTR + c + 3], v.w);
        }
        __syncthreads();

        #pragma unroll
        for (int kk = 0; kk < 32; kk += 16) {
            unsigned ah[4][4], al[4][4], bh[4][2], bl[4][2];
            #pragma unroll
            for (int mi = 0; mi < 4; mi++) {
                const int off = (wm + mi * 16 + (lane & 15)) * ASTR + kk + (lane >> 4) * 8;
                ldsm4(ah[mi][0], ah[mi][1], ah[mi][2], ah[mi][3], smem_u32(&sAh[off]));
                ldsm4(al[mi][0], al[mi][1], al[mi][2], al[mi][3], smem_u32(&sAl[off]));
            }
            #pragma unroll
            for (int np = 0; np < 2; np++) {
                const int off = (kk + (lane & 15)) * BSTR + wn + np * 16 + (lane >> 4) * 8;
                ldsm4t(bh[np*2][0], bh[np*2][1], bh[np*2+1][0], bh[np*2+1][1],
                       smem_u32(&sBh[off]));
                ldsm4t(bl[np*2][0], bl[np*2][1], bl[np*2+1][0], bl[np*2+1][1],
                       smem_u32(&sBl[off]));
            }
            #pragma unroll
            for (int mi = 0; mi < 4; mi++)
                #pragma unroll
                for (int nj = 0; nj < 4; nj++) {
                    mma16816(acc[mi][nj], ah[mi], bh[nj]);
                    mma16816(acc[mi][nj], ah[mi], bl[nj]);
                    mma16816(acc[mi][nj], al[mi], bh[nj]);
                }
        }
        __syncthreads();
    }

    const int g = lane >> 2, t = lane & 3;
    #pragma unroll
    for (int mi = 0; mi < 4; mi++) {
        #pragma unroll
        for (int nj = 0; nj < 4; nj++) {
            const int r = row0 + wm + mi * 16 + g;
            const int c = col0 + wn + nj * 8 + t * 2;
            const int oc = (head_in > 0)
                ? (c / head_in) * DQK + head_off + (c % head_in) : c;
            *(float2*)(C + (long)r * ldc + oc) =
                make_float2(acc[mi][nj][0], acc[mi][nj][1]);
            *(float2*)(C + (long)(r + 8) * ldc + oc) =
                make_float2(acc[mi][nj][2], acc[mi][nj][3]);
        }
    }
}

// =====================================================================
// 128x128x16 fp32 SGEMM (kept for PV with causal + batching)
// =====================================================================
#define TM 128
#define TN 128
#define TKS 16

__global__ __launch_bounds__(256)
void sgemm128_kernel(const float* __restrict__ A, long Ao, long Ai,
                     const float* __restrict__ Bp, long Bo, long Bi,
                     float* __restrict__ C, long Co, long Ci,
                     int zmod, int lda, int ldb, int ldc,
                     int K, int head_in, int head_off, int causal)
{
    const int z  = blockIdx.z;
    const float* Ab = A  + (long)(z / zmod) * Ao + (long)(z % zmod) * Ai;
    const float* Bb = Bp + (long)(z / zmod) * Bo + (long)(z % zmod) * Bi;
    float*       Cb = C  + (long)(z / zmod) * Co + (long)(z % zmod) * Ci;

    const int row0 = blockIdx.y * TM;
    const int col0 = blockIdx.x * TN;
    const int Keff = causal ? min(K, (int)(blockIdx.y + 1) * TM) : K;

    __shared__ float As[TKS][TM];
    __shared__ float Bs[TKS][TN];

    const int tid = threadIdx.x;
    const int ty = tid >> 4, tx = tid & 15;

    float acc[8][8] = {};

    for (int k0 = 0; k0 < Keff; k0 += TKS) {
        #pragma unroll
        for (int m = 0; m < 2; m++) {
            const int f = tid * 2 + m;
            const int r = f >> 2;
            const int c = (f & 3) * 4;
            float4 av = *(const float4*)(Ab + (long)(row0 + r) * lda + k0 + c);
            As[c + 0][r] = av.x;
            As[c + 1][r] = av.y;
            As[c + 2][r] = av.z;
            As[c + 3][r] = av.w;
        }
        #pragma unroll
        for (int m = 0; m < 2; m++) {
            const int f = tid * 2 + m;
            const int r = f >> 5;
            const int c = (f & 31) * 4;
            *(float4*)&Bs[r][c] =
                *(const float4*)(Bb + (long)(k0 + r) * ldb + col0 + c);
        }
        __syncthreads();

        #pragma unroll
        for (int kk = 0; kk < TKS; kk++) {
            float a[8], b[8];
            *(float4*)(a + 0) = *(const float4*)&As[kk][ty * 4];
            *(float4*)(a + 4) = *(const float4*)&As[kk][64 + ty * 4];
            *(float4*)(b + 0) = *(const float4*)&Bs[kk][tx * 4];
            *(float4*)(b + 4) = *(const float4*)&Bs[kk][64 + tx * 4];
            #pragma unroll
            for (int i = 0; i < 8; i++)
                #pragma unroll
                for (int j = 0; j < 8; j++)
                    acc[i][j] = fmaf(a[i], b[j], acc[i][j]);
        }
        __syncthreads();
    }

    #pragma unroll
    for (int i = 0; i < 8; i++) {
        const int r = row0 + ((i < 4) ? (ty * 4 + i) : (64 + ty * 4 + i - 4));
        #pragma unroll
        for (int j = 0; j < 8; j++) {
            const int c = col0 + ((j < 4) ? (tx * 4 + j) : (64 + tx * 4 + j - 4));
            const int oc = (head_in > 0)
                ? (c / head_in) * DQK + head_off + (c % head_in) : c;
            Cb[(long)r * ldc + oc] = acc[i][j];
        }
    }
}

// =====================================================================
// scores: S = Q Kt * SCALE, causal masked (128x128 tiles), fp32
// =====================================================================
__global__ __launch_bounds__(256)
void scores128_kernel(const float* __restrict__ q, const float* __restrict__ k,
                      float* __restrict__ sc)
{
    const int kt = blockIdx.x, qt = blockIdx.y, z = blockIdx.z;
    if (kt > qt) return;
    const int b = z >> 4, h = z & 15;
    const float* qb = q + (long)b * TT * HH * DQK + (long)h * DQK;
    const float* kb = k + (long)b * TT * HH * DQK + (long)h * DQK;
    const int q0 = qt * TM, k0 = kt * TN;
    const int RS = HH * DQK;   // 3072

    __shared__ float Qs[TKS][TM];
    __shared__ float Ks[TKS][TN];

    const int tid = threadIdx.x;
    const int ty = tid >> 4, tx = tid & 15;

    float acc[8][8] = {};

    for (int d0 = 0; d0 < DQK; d0 += TKS) {
        #pragma unroll
        for (int m = 0; m < 2; m++) {
            const int f = tid * 2 + m;
            const int r = f >> 2;
            const int c = (f & 3) * 4;
            float4 qv = *(const float4*)(qb + (long)(q0 + r) * RS + d0 + c);
            Qs[c + 0][r] = qv.x; Qs[c + 1][r] = qv.y;
            Qs[c + 2][r] = qv.z; Qs[c + 3][r] = qv.w;
            float4 kv = *(const float4*)(kb + (long)(k0 + r) * RS + d0 + c);
            Ks[c + 0][r] = kv.x; Ks[c + 1][r] = kv.y;
            Ks[c + 2][r] = kv.z; Ks[c + 3][r] = kv.w;
        }
        __syncthreads();
        #pragma unroll
        for (int kk = 0; kk < TKS; kk++) {
            float a[8], b2[8];
            *(float4*)(a + 0)  = *(const float4*)&Qs[kk][ty * 4];
            *(float4*)(a + 4)  = *(const float4*)&Qs[kk][64 + ty * 4];
            *(float4*)(b2 + 0) = *(const float4*)&Ks[kk][tx * 4];
            *(float4*)(b2 + 4) = *(const float4*)&Ks[kk][64 + tx * 4];
            #pragma unroll
            for (int i = 0; i < 8; i++)
                #pragma unroll
                for (int j = 0; j < 8; j++)
                    acc[i][j] = fmaf(a[i], b2[j], acc[i][j]);
        }
        __syncthreads();
    }

    float* out = sc + (long)z * TT * TT;
    #pragma unroll
    for (int i = 0; i < 8; i++) {
        const int qi = q0 + ((i < 4) ? (ty * 4 + i) : (64 + ty * 4 + i - 4));
        #pragma unroll
        for (int j = 0; j < 8; j++) {
            const int kj = k0 + ((j < 4) ? (tx * 4 + j) : (64 + tx * 4 + j - 4));
            float v = acc[i][j] * SCALE;
            if (qt == kt && kj > qi) v = -INFINITY;
            out[(long)qi * TT + kj] = v;
        }
    }
}

// ---------------- 64x64 SGEMM (W_KR, N=64) ----------------
#define BM 64
#define BN 64
#define BKT 16

__global__ __launch_bounds__(256)
void sgemm_kernel(const float* __restrict__ A, long Ao, long Ai,
                  const float* __restrict__ Bp, long Bo, long Bi,
                  float* __restrict__ C, long Co, long Ci,
                  int zmod, int lda, int ldb, int ldc,
                  int K, int head_in, int head_off, int causal)
{
    const int z  = blockIdx.z;
    const float* Ab = A  + (long)(z / zmod) * Ao + (long)(z % zmod) * Ai;
    const float* Bb = Bp + (long)(z / zmod) * Bo + (long)(z % zmod) * Bi;
    float*       Cb = C  + (long)(z / zmod) * Co + (long)(z % zmod) * Ci;

    const int row0 = blockIdx.y * BM;
    const int col0 = blockIdx.x * BN;
    const int Keff = causal ? min(K, (int)(blockIdx.y + 1) * BM) : K;

    __shared__ float As[BKT][BM];
    __shared__ float Bs[BKT][BN];

    const int tid = threadIdx.x;
    const int tx = tid & 15, ty = tid >> 4;
    const int arow = tid >> 2,  acol = (tid & 3) * 4;
    const int brow = tid >> 4,  bcol = (tid & 15) * 4;

    float acc[4][4] = {};

    for (int k0 = 0; k0 < Keff; k0 += BKT) {
        float4 av = *(const float4*)(Ab + (long)(row0 + arow) * lda + k0 + acol);
        As[acol + 0][arow] = av.x;
        As[acol + 1][arow] = av.y;
        As[acol + 2][arow] = av.z;
        As[acol + 3][arow] = av.w;
        float4 bv = *(const float4*)(Bb + (long)(k0 + brow) * ldb + col0 + bcol);
        *(float4*)&Bs[brow][bcol] = bv;
        __syncthreads();
        #pragma unroll
        for (int kk = 0; kk < BKT; kk++) {
            float4 af = *(const float4*)&As[kk][ty * 4];
            float4 bf = *(const float4*)&Bs[kk][tx * 4];
            float a0[4] = {af.x, af.y, af.z, af.w};
            float b0[4] = {bf.x, bf.y, bf.z, bf.w};
            #pragma unroll
            for (int i = 0; i < 4; i++)
                #pragma unroll
                for (int j = 0; j < 4; j++)
                    acc[i][j] = fmaf(a0[i], b0[j], acc[i][j]);
        }
        __syncthreads();
    }

    #pragma unroll
    for (int i = 0; i < 4; i++) {
        const int r = row0 + ty * 4 + i;
        #pragma unroll
        for (int j = 0; j < 4; j++) {
            int c = col0 + tx * 4 + j;
            int oc = (head_in > 0) ? (c / head_in) * DQK + head_off + (c % head_in) : c;
            Cb[(long)r * ldc + oc] = acc[i][j];
        }
    }
}

// ---------------- RMSNorm in place (one block per row) ----------------
__global__ __launch_bounds__(256)
void rmsnorm_kernel(float* __restrict__ x, const float* __restrict__ w, int len)
{
    float* p = x + (long)blockIdx.x * len;
    __shared__ float red[256];
    const int tid = threadIdx.x;
    float s = 0.f;
    for (int i = tid; i < len; i += 256) { float v = p[i]; s += v * v; }
    red[tid] = s; __syncthreads();
    for (int d = 128; d > 0; d >>= 1) { if (tid < d) red[tid] += red[tid + d]; __syncthreads(); }
    const float inv = rsqrtf(red[0] / (float)len + EPS);
    for (int i = tid; i < len; i += 256) p[i] = p[i] * inv * w[i];
}

// ---------------- RoPE on q rope slice (in place) ----------------
__global__ void rope_q_kernel(float* __restrict__ q)
{
    long idx = (long)blockIdx.x * blockDim.x + threadIdx.x;   // B*T*H*32
    if (idx >= (long)NTOK * HH * 32) return;
    const int i = idx & 31;
    const int h = (idx >> 5) & 15;
    const long tok = idx >> 9;
    const int t = (int)(tok & (TT - 1));
    const float inv = powf(500000.0f, -(float)i / 32.0f);
    float c, s;
    sincosf((float)t * inv, &s, &c);
    float* p = q + tok * (HH * DQK) + (long)h * DQK + DH;
    const float a = p[i], b = p[i + 32];
    p[i]      = a * c - b * s;
    p[i + 32] = b * c + a * s;
}

// ---------------- RoPE on k_R + broadcast into g_k for all heads ----------------
__global__ void rope_k_kernel(const float* __restrict__ kR, float* __restrict__ k)
{
    long idx = (long)blockIdx.x * blockDim.x + threadIdx.x;   // B*T*32
    if (idx >= (long)NTOK * 32) return;
    const int i = idx & 31;
    const long tok = idx >> 5;
    const int t = (int)(tok & (TT - 1));
    const float inv = powf(500000.0f, -(float)i / 32.0f);
    float c, s;
    sincosf((float)t * inv, &s, &c);
    const float a = kR[tok * DR + i], b = kR[tok * DR + i + 32];
    const float r0 = a * c - b * s;
    const float r1 = b * c + a * s;
    float* base = k + tok * (HH * DQK) + DH;
    #pragma unroll
    for (int h = 0; h < HH; h++) {
        base[(long)h * DQK + i]      = r0;
        base[(long)h * DQK + i + 32] = r1;
    }
}

// ---------------- row softmax (causal length, 128-tile granularity) ----------------
__global__ __launch_bounds__(256)
void softmax_kernel(float* __restrict__ sc)
{
    const int qpos = blockIdx.x, z = blockIdx.y;
    float* row = sc + ((long)z * TT + qpos) * TT;
    const int kend = ((qpos >> 7) + 1) << 7;      // 128-tile padded; masked -inf -> 0
    __shared__ float buf[2048];
    __shared__ float red[256];
    const int tid = threadIdx.x;

    float m = -INFINITY;
    for (int i = tid; i < kend; i += 256) m = fmaxf(m, row[i]);
    red[tid] = m; __syncthreads();
    for (int d = 128; d > 0; d >>= 1) { if (tid < d) red[tid] = fmaxf(red[tid], red[tid + d]); __syncthreads(); }
    m = red[0]; __syncthreads();

    float s = 0.f;
    for (int i = tid; i < kend; i += 256) { float e = expf(row[i] - m); buf[i] = e; s += e; }
    red[tid] = s; __syncthreads();
    for (int d = 128; d > 0; d >>= 1) { if (tid < d) red[tid] += red[tid + d]; __syncthreads(); }
    const float inv = 1.0f / red[0];
    for (int i = tid; i < kend; i += 256) row[i] = buf[i] * inv;
}

// ---------------- launch ----------------
extern "C" void kernel_launch(void* const* d_in, const int* in_sizes, int n_in,
                              void* d_out, int out_size)
{
    const float* x     = (const float*)d_in[0];
    const float* W_DQ  = (const float*)d_in[1];
    const float* W_UQ  = (const float*)d_in[2];
    const float* W_QR  = (const float*)d_in[3];
    const float* W_DKV = (const float*)d_in[4];
    const float* W_UK  = (const float*)d_in[5];
    const float* W_UV  = (const float*)d_in[6];
    const float* W_KR  = (const float*)d_in[7];
    const float* W_O   = (const float*)d_in[8];
    const float* qnw   = (const float*)d_in[9];
    const float* kvnw  = (const float*)d_in[10];
    float* out = (float*)d_out;

    float *cQ, *cKV, *q, *k, *v, *kR, *sc, *ao;
    cudaGetSymbolAddress((void**)&cQ,  g_cQ);
    cudaGetSymbolAddress((void**)&cKV, g_cKV);
    cudaGetSymbolAddress((void**)&q,   g_q);
    cudaGetSymbolAddress((void**)&k,   g_k);
    cudaGetSymbolAddress((void**)&v,   g_v);
    cudaGetSymbolAddress((void**)&kR,  g_kR);
    cudaGetSymbolAddress((void**)&sc,  g_sc);
    cudaGetSymbolAddress((void**)&ao,  g_ao);

    const dim3 blk(256);

    // 1) c_Q = x @ W_DQ ; RMSNorm
    bgemm_kernel<<<dim3(DQ/128, NTOK/128), blk>>>(x, W_DQ, cQ, DD, DQ, DQ, DD, 0, 0);
    rmsnorm_kernel<<<NTOK, blk>>>(cQ, qnw, DQ);

    // 2) c_KV = x @ W_DKV ; RMSNorm
    bgemm_kernel<<<dim3(DKV/128, NTOK/128), blk>>>(x, W_DKV, cKV, DD, DKV, DKV, DD, 0, 0);
    rmsnorm_kernel<<<NTOK, blk>>>(cKV, kvnw, DKV);

    // 3) q content + rope parts into g_q (B,T,H,192)
    bgemm_kernel<<<dim3((HH*DH)/128, NTOK/128), blk>>>(cQ, W_UQ, q, DQ, HH*DH, HH*DQK, DQ, DH, 0);
    bgemm_kernel<<<dim3((HH*DR)/128, NTOK/128), blk>>>(cQ, W_QR, q, DQ, HH*DR, HH*DQK, DQ, DR, DH);

    // 4) k content into g_k ; v into g_v (plain B,T,H*128)
    bgemm_kernel<<<dim3((HH*DH)/128, NTOK/128), blk>>>(cKV, W_UK, k, DKV, HH*DH, HH*DQK, DKV, DH, 0);
    bgemm_kernel<<<dim3((HH*DH)/128, NTOK/128), blk>>>(cKV, W_UV, v, DKV, HH*DH, HH*DH, DKV, 0, 0);

    // 5) k_R = x @ W_KR  (N=64 -> fp32 64-wide kernel)
    sgemm_kernel<<<dim3(DR/64, NTOK/64, 1), blk>>>(x,0,0, W_KR,0,0, kR,0,0,
        1, DD, DR, DR, DD, 0,0,0);

    // 6) RoPE
    rope_q_kernel<<<((long)NTOK*HH*32 + 255)/256, blk>>>(q);
    rope_k_kernel<<<((long)NTOK*32 + 255)/256, blk>>>(kR, k);

    // 7) attention: scores -> softmax -> PV (fp32)
    scores128_kernel<<<dim3(TT/128, TT/128, BHZ), blk>>>(q, k, sc);
    softmax_kernel<<<dim3(TT, BHZ), blk>>>(sc);

    sgemm128_kernel<<<dim3(DH/128, TT/128, BHZ), blk>>>(
        sc, (long)HH*TT*TT, (long)TT*TT,
        v,  (long)TT*HH*DH, (long)DH,
        ao, (long)TT*HH*DH, (long)DH,
        HH, TT, HH*DH, HH*DH,
        TT, 0, 0, 1);

    // 8) final: out = ao @ W_O
    bgemm_kernel<<<dim3(DD/128, NTOK/128), blk>>>(ao, W_O, out, HH*DH, DD, DD, HH*DH, 0, 0);
}

// round 8
// speedup vs baseline: 2.4990x; 1.3634x over previous
#include <cuda_runtime.h>
#include <cuda_bf16.h>
#include <cstdint>
#include <math.h>

// ---------------- problem constants ----------------
#define BATCH 2
#define TT    2048
#define DD    2048
#define HH    16
#define DH    128
#define DKV   512
#define DQ    1024
#define DR    64
#define DQK   192            // DH + DR
#define NTOK  (BATCH*TT)     // 4096
#define BHZ   (BATCH*HH)     // 32
#define EPS   1e-6f
#define SCALE 0.072168783648703220563f   // 1/sqrt(192)

// ---------------- scratch (device globals; allocation-free) ----------------
__device__ __align__(16) float g_cQ   [(size_t)NTOK * DQ];
__device__ __align__(16) float g_cKV  [(size_t)NTOK * DKV];
__device__ __align__(16) float g_q    [(size_t)NTOK * HH * DQK];
__device__ __align__(16) float g_k    [(size_t)NTOK * HH * DQK];
__device__ __align__(16) float g_v    [(size_t)NTOK * HH * DH];
__device__ __align__(16) float g_kR   [(size_t)NTOK * DR];
__device__ __align__(16) float g_sc   [(size_t)BHZ * TT * TT];
__device__ __align__(16) float g_ao   [(size_t)NTOK * HH * DH];

// =====================================================================
// mma.sync helpers (bf16 hi/lo split for fp32-grade accuracy)
// =====================================================================
#define ASTR 40     // smem row stride (bf16) for 32-wide K-step tiles
#define BSTR 136    // smem row stride (bf16) for 128-wide B tiles

__device__ __forceinline__ unsigned smem_u32(const void* p) {
    return (unsigned)__cvta_generic_to_shared(p);
}
__device__ __forceinline__ void ldsm4(unsigned& r0, unsigned& r1,
                                      unsigned& r2, unsigned& r3, unsigned a) {
    asm volatile("ldmatrix.sync.aligned.m8n8.x4.shared.b16 {%0,%1,%2,%3}, [%4];"
                 : "=r"(r0), "=r"(r1), "=r"(r2), "=r"(r3) : "r"(a));
}
__device__ __forceinline__ void ldsm4t(unsigned& r0, unsigned& r1,
                                       unsigned& r2, unsigned& r3, unsigned a) {
    asm volatile("ldmatrix.sync.aligned.m8n8.x4.trans.shared.b16 {%0,%1,%2,%3}, [%4];"
                 : "=r"(r0), "=r"(r1), "=r"(r2), "=r"(r3) : "r"(a));
}
__device__ __forceinline__ void mma16816(float* d, const unsigned* a, const unsigned* b) {
    asm volatile("mma.sync.aligned.m16n8k16.row.col.f32.bf16.bf16.f32 "
                 "{%0,%1,%2,%3}, {%4,%5,%6,%7}, {%8,%9}, {%0,%1,%2,%3};"
                 : "+f"(d[0]), "+f"(d[1]), "+f"(d[2]), "+f"(d[3])
                 : "r"(a[0]), "r"(a[1]), "r"(a[2]), "r"(a[3]),
                   "r"(b[0]), "r"(b[1]));
}
__device__ __forceinline__ void split_store(__nv_bfloat16* hi, __nv_bfloat16* lo, float v) {
    __nv_bfloat16 h = __float2bfloat16(v);
    *hi = h;
    *lo = __float2bfloat16(v - __bfloat162float(h));
}

// =====================================================================
// Batched tensor-core GEMM, fp32 via hi/lo split.
// C[z] (M x N) = A[z] (M x K) * B[z] (K x N), row-major.
// base(z) = ptr + (z/zmod)*outer + (z%zmod)*inner
// head_in>0 remaps out col j -> (j/head_in)*DQK + head_off + (j%head_in)
// causal!=0 clamps K to (blockIdx.y+1)*128
// =====================================================================
__global__ __launch_bounds__(256)
void bgemm_kernel(const float* __restrict__ A, long Ao, long Ai,
                  const float* __restrict__ B, long Bo, long Bi,
                  float* __restrict__ C, long Co, long Ci,
                  int zmod, int lda, int ldb, int ldc,
                  int K, int head_in, int head_off, int causal)
{
    __shared__ __align__(16) __nv_bfloat16 sAh[128 * ASTR];
    __shared__ __align__(16) __nv_bfloat16 sAl[128 * ASTR];
    __shared__ __align__(16) __nv_bfloat16 sBh[32 * BSTR];
    __shared__ __align__(16) __nv_bfloat16 sBl[32 * BSTR];

    const int z = blockIdx.z;
    const float* Ab = A + (long)(z / zmod) * Ao + (long)(z % zmod) * Ai;
    const float* Bb = B + (long)(z / zmod) * Bo + (long)(z % zmod) * Bi;
    float*       Cb = C + (long)(z / zmod) * Co + (long)(z % zmod) * Ci;

    const int tid = threadIdx.x;
    const int wid = tid >> 5, lane = tid & 31;
    const int wm = (wid & 1) * 64;
    const int wn = (wid >> 1) * 32;
    const int row0 = blockIdx.y * 128;
    const int col0 = blockIdx.x * 128;
    const int Keff = causal ? min(K, (int)(blockIdx.y + 1) * 128) : K;

    float acc[4][4][4];
    #pragma unroll
    for (int i = 0; i < 4; i++)
        #pragma unroll
        for (int j = 0; j < 4; j++)
            #pragma unroll
            for (int r = 0; r < 4; r++) acc[i][j][r] = 0.f;

    for (int k0 = 0; k0 < Keff; k0 += 32) {
        #pragma unroll
        for (int m = 0; m < 4; m++) {
            const int f = tid + m * 256;
            const int r = f >> 3;
            const int c = (f & 7) * 4;
            float4 v = *(const float4*)(Ab + (long)(row0 + r) * lda + k0 + c);
            split_store(&sAh[r * ASTR + c + 0], &sAl[r * ASTR + c + 0], v.x);
            split_store(&sAh[r * ASTR + c + 1], &sAl[r * ASTR + c + 1], v.y);
            split_store(&sAh[r * ASTR + c + 2], &sAl[r * ASTR + c + 2], v.z);
            split_store(&sAh[r * ASTR + c + 3], &sAl[r * ASTR + c + 3], v.w);
        }
        #pragma unroll
        for (int m = 0; m < 4; m++) {
            const int f = tid + m * 256;
            const int r = f >> 5;
            const int c = (f & 31) * 4;
            float4 v = *(const float4*)(Bb + (long)(k0 + r) * ldb + col0 + c);
            split_store(&sBh[r * BSTR + c + 0], &sBl[r * BSTR + c + 0], v.x);
            split_store(&sBh[r * BSTR + c + 1], &sBl[r * BSTR + c + 1], v.y);
            split_store(&sBh[r * BSTR + c + 2], &sBl[r * BSTR + c + 2], v.z);
            split_store(&sBh[r * BSTR + c + 3], &sBl[r * BSTR + c + 3], v.w);
        }
        __syncthreads();

        #pragma unroll
        for (int kk = 0; kk < 32; kk += 16) {
            unsigned ah[4][4], al[4][4], bh[4][2], bl[4][2];
            #pragma unroll
            for (int mi = 0; mi < 4; mi++) {
                const int off = (wm + mi * 16 + (lane & 15)) * ASTR + kk + (lane >> 4) * 8;
                ldsm4(ah[mi][0], ah[mi][1], ah[mi][2], ah[mi][3], smem_u32(&sAh[off]));
                ldsm4(al[mi][0], al[mi][1], al[mi][2], al[mi][3], smem_u32(&sAl[off]));
            }
            #pragma unroll
            for (int np = 0; np < 2; np++) {
                const int off = (kk + (lane & 15)) * BSTR + wn + np * 16 + (lane >> 4) * 8;
                ldsm4t(bh[np*2][0], bh[np*2][1], bh[np*2+1][0], bh[np*2+1][1],
                       smem_u32(&sBh[off]));
                ldsm4t(bl[np*2][0], bl[np*2][1], bl[np*2+1][0], bl[np*2+1][1],
                       smem_u32(&sBl[off]));
            }
            #pragma unroll
            for (int mi = 0; mi < 4; mi++)
                #pragma unroll
                for (int nj = 0; nj < 4; nj++) {
                    mma16816(acc[mi][nj], ah[mi], bh[nj]);
                    mma16816(acc[mi][nj], ah[mi], bl[nj]);
                    mma16816(acc[mi][nj], al[mi], bh[nj]);
                }
        }
        __syncthreads();
    }

    const int g = lane >> 2, t = lane & 3;
    #pragma unroll
    for (int mi = 0; mi < 4; mi++) {
        #pragma unroll
        for (int nj = 0; nj < 4; nj++) {
            const int r = row0 + wm + mi * 16 + g;
            const int c = col0 + wn + nj * 8 + t * 2;
            const int oc = (head_in > 0)
                ? (c / head_in) * DQK + head_off + (c % head_in) : c;
            *(float2*)(Cb + (long)r * ldc + oc) =
                make_float2(acc[mi][nj][0], acc[mi][nj][1]);
            *(float2*)(Cb + (long)(r + 8) * ldc + oc) =
                make_float2(acc[mi][nj][2], acc[mi][nj][3]);
        }
    }
}

// =====================================================================
// Tensor-core scores: S = Q Kt * SCALE, causal masked.
// Q,K layout (B,T,H,192) row-major, row stride 3072.
// B-operand = K row-major == Kt col-major -> NON-trans ldmatrix,
// fragments {r0,r2} (n 0-7) and {r1,r3} (n 8-15).
// =====================================================================
__global__ __launch_bounds__(256)
void scores_mma_kernel(const float* __restrict__ q, const float* __restrict__ k,
                       float* __restrict__ sc)
{
    const int kt = blockIdx.x, qt = blockIdx.y, z = blockIdx.z;
    if (kt > qt) return;
    const int b = z >> 4, h = z & 15;
    const float* qb = q + (long)b * TT * HH * DQK + (long)h * DQK;
    const float* kb = k + (long)b * TT * HH * DQK + (long)h * DQK;
    const int q0 = qt * 128, k0 = kt * 128;
    const int RS = HH * DQK;   // 3072

    __shared__ __align__(16) __nv_bfloat16 sQh[128 * ASTR];
    __shared__ __align__(16) __nv_bfloat16 sQl[128 * ASTR];
    __shared__ __align__(16) __nv_bfloat16 sKh[128 * ASTR];
    __shared__ __align__(16) __nv_bfloat16 sKl[128 * ASTR];

    const int tid = threadIdx.x;
    const int wid = tid >> 5, lane = tid & 31;
    const int wm = (wid & 1) * 64;
    const int wn = (wid >> 1) * 32;

    float acc[4][4][4];
    #pragma unroll
    for (int i = 0; i < 4; i++)
        #pragma unroll
        for (int j = 0; j < 4; j++)
            #pragma unroll
            for (int r = 0; r < 4; r++) acc[i][j][r] = 0.f;

    for (int d0 = 0; d0 < DQK; d0 += 32) {
        #pragma unroll
        for (int m = 0; m < 4; m++) {
            const int f = tid + m * 256;
            const int r = f >> 3;
            const int c = (f & 7) * 4;
            float4 v = *(const float4*)(qb + (long)(q0 + r) * RS + d0 + c);
            split_store(&sQh[r * ASTR + c + 0], &sQl[r * ASTR + c + 0], v.x);
            split_store(&sQh[r * ASTR + c + 1], &sQl[r * ASTR + c + 1], v.y);
            split_store(&sQh[r * ASTR + c + 2], &sQl[r * ASTR + c + 2], v.z);
            split_store(&sQh[r * ASTR + c + 3], &sQl[r * ASTR + c + 3], v.w);
            float4 w = *(const float4*)(kb + (long)(k0 + r) * RS + d0 + c);
            split_store(&sKh[r * ASTR + c + 0], &sKl[r * ASTR + c + 0], w.x);
            split_store(&sKh[r * ASTR + c + 1], &sKl[r * ASTR + c + 1], w.y);
            split_store(&sKh[r * ASTR + c + 2], &sKl[r * ASTR + c + 2], w.z);
            split_store(&sKh[r * ASTR + c + 3], &sKl[r * ASTR + c + 3], w.w);
        }
        __syncthreads();

        #pragma unroll
        for (int kk = 0; kk < 32; kk += 16) {
            unsigned ah[4][4], al[4][4], bh[4][2], bl[4][2];
            #pragma unroll
            for (int mi = 0; mi < 4; mi++) {
                const int off = (wm + mi * 16 + (lane & 15)) * ASTR + kk + (lane >> 4) * 8;
                ldsm4(ah[mi][0], ah[mi][1], ah[mi][2], ah[mi][3], smem_u32(&sQh[off]));
                ldsm4(al[mi][0], al[mi][1], al[mi][2], al[mi][3], smem_u32(&sQl[off]));
            }
            #pragma unroll
            for (int np = 0; np < 2; np++) {
                const int off = (wn + np * 16 + (lane & 15)) * ASTR + kk + (lane >> 4) * 8;
                unsigned r0, r1, r2, r3;
                ldsm4(r0, r1, r2, r3, smem_u32(&sKh[off]));
                bh[np*2][0] = r0; bh[np*2][1] = r2;
                bh[np*2+1][0] = r1; bh[np*2+1][1] = r3;
                ldsm4(r0, r1, r2, r3, smem_u32(&sKl[off]));
                bl[np*2][0] = r0; bl[np*2][1] = r2;
                bl[np*2+1][0] = r1; bl[np*2+1][1] = r3;
            }
            #pragma unroll
            for (int mi = 0; mi < 4; mi++)
                #pragma unroll
                for (int nj = 0; nj < 4; nj++) {
                    mma16816(acc[mi][nj], ah[mi], bh[nj]);
                    mma16816(acc[mi][nj], ah[mi], bl[nj]);
                    mma16816(acc[mi][nj], al[mi], bh[nj]);
                }
        }
        __syncthreads();
    }

    float* out = sc + (long)z * TT * TT;
    const int g = lane >> 2, t = lane & 3;
    #pragma unroll
    for (int mi = 0; mi < 4; mi++) {
        #pragma unroll
        for (int nj = 0; nj < 4; nj++) {
            #pragma unroll
            for (int rr = 0; rr < 2; rr++) {
                const int qi = q0 + wm + mi * 16 + g + rr * 8;
                const int kj = k0 + wn + nj * 8 + t * 2;
                float v0 = acc[mi][nj][rr * 2 + 0] * SCALE;
                float v1 = acc[mi][nj][rr * 2 + 1] * SCALE;
                if (qt == kt) {
                    if (kj + 0 > qi) v0 = -INFINITY;
                    if (kj + 1 > qi) v1 = -INFINITY;
                }
                *(float2*)(out + (long)qi * TT + kj) = make_float2(v0, v1);
            }
        }
    }
}

// ---------------- 64x64 fp32 SGEMM (W_KR, N=64) ----------------
#define BM 64
#define BN 64
#define BKT 16

__global__ __launch_bounds__(256)
void sgemm_kernel(const float* __restrict__ A,
                  const float* __restrict__ Bp,
                  float* __restrict__ C,
                  int lda, int ldb, int ldc, int K)
{
    const int row0 = blockIdx.y * BM;
    const int col0 = blockIdx.x * BN;

    __shared__ float As[BKT][BM];
    __shared__ float Bs[BKT][BN];

    const int tid = threadIdx.x;
    const int tx = tid & 15, ty = tid >> 4;
    const int arow = tid >> 2,  acol = (tid & 3) * 4;
    const int brow = tid >> 4,  bcol = (tid & 15) * 4;

    float acc[4][4] = {};

    for (int k0 = 0; k0 < K; k0 += BKT) {
        float4 av = *(const float4*)(A + (long)(row0 + arow) * lda + k0 + acol);
        As[acol + 0][arow] = av.x;
        As[acol + 1][arow] = av.y;
        As[acol + 2][arow] = av.z;
        As[acol + 3][arow] = av.w;
        float4 bv = *(const float4*)(Bp + (long)(k0 + brow) * ldb + col0 + bcol);
        *(float4*)&Bs[brow][bcol] = bv;
        __syncthreads();
        #pragma unroll
        for (int kk = 0; kk < BKT; kk++) {
            float4 af = *(const float4*)&As[kk][ty * 4];
            float4 bf = *(const float4*)&Bs[kk][tx * 4];
            float a0[4] = {af.x, af.y, af.z, af.w};
            float b0[4] = {bf.x, bf.y, bf.z, bf.w};
            #pragma unroll
            for (int i = 0; i < 4; i++)
                #pragma unroll
                for (int j = 0; j < 4; j++)
                    acc[i][j] = fmaf(a0[i], b0[j], acc[i][j]);
        }
        __syncthreads();
    }

    #pragma unroll
    for (int i = 0; i < 4; i++) {
        const int r = row0 + ty * 4 + i;
        #pragma unroll
        for (int j = 0; j < 4; j++)
            C[(long)r * ldc + col0 + tx * 4 + j] = acc[i][j];
    }
}

// ---------------- RMSNorm in place (one block per row) ----------------
__global__ __launch_bounds__(256)
void rmsnorm_kernel(float* __restrict__ x, const float* __restrict__ w, int len)
{
    float* p = x + (long)blockIdx.x * len;
    __shared__ float red[256];
    const int tid = threadIdx.x;
    float s = 0.f;
    for (int i = tid; i < len; i += 256) { float v = p[i]; s += v * v; }
    red[tid] = s; __syncthreads();
    for (int d = 128; d > 0; d >>= 1) { if (tid < d) red[tid] += red[tid + d]; __syncthreads(); }
    const float inv = rsqrtf(red[0] / (float)len + EPS);
    for (int i = tid; i < len; i += 256) p[i] = p[i] * inv * w[i];
}

// ---------------- RoPE on q rope slice (in place) ----------------
__global__ void rope_q_kernel(float* __restrict__ q)
{
    long idx = (long)blockIdx.x * blockDim.x + threadIdx.x;   // B*T*H*32
    if (idx >= (long)NTOK * HH * 32) return;
    const int i = idx & 31;
    const int h = (idx >> 5) & 15;
    const long tok = idx >> 9;
    const int t = (int)(tok & (TT - 1));
    const float inv = powf(500000.0f, -(float)i / 32.0f);
    float c, s;
    sincosf((float)t * inv, &s, &c);
    float* p = q + tok * (HH * DQK) + (long)h * DQK + DH;
    const float a = p[i], b = p[i + 32];
    p[i]      = a * c - b * s;
    p[i + 32] = b * c + a * s;
}

// ---------------- RoPE on k_R + broadcast into g_k for all heads ----------------
__global__ void rope_k_kernel(const float* __restrict__ kR, float* __restrict__ k)
{
    long idx = (long)blockIdx.x * blockDim.x + threadIdx.x;   // B*T*32
    if (idx >= (long)NTOK * 32) return;
    const int i = idx & 31;
    const long tok = idx >> 5;
    const int t = (int)(tok & (TT - 1));
    const float inv = powf(500000.0f, -(float)i / 32.0f);
    float c, s;
    sincosf((float)t * inv, &s, &c);
    const float a = kR[tok * DR + i], b = kR[tok * DR + i + 32];
    const float r0 = a * c - b * s;
    const float r1 = b * c + a * s;
    float* base = k + tok * (HH * DQK) + DH;
    #pragma unroll
    for (int h = 0; h < HH; h++) {
        base[(long)h * DQK + i]      = r0;
        base[(long)h * DQK + i + 32] = r1;
    }
}

// ---------------- row softmax (causal length, 128-tile granularity) ----------------
__global__ __launch_bounds__(256)
void softmax_kernel(float* __restrict__ sc)
{
    const int qpos = blockIdx.x, z = blockIdx.y;
    float* row = sc + ((long)z * TT + qpos) * TT;
    const int kend = ((qpos >> 7) + 1) << 7;      // 128-tile padded; masked -inf -> 0
    __shared__ float buf[2048];
    __shared__ float red[256];
    const int tid = threadIdx.x;

    float m = -INFINITY;
    for (int i = tid; i < kend; i += 256) m = fmaxf(m, row[i]);
    red[tid] = m; __syncthreads();
    for (int d = 128; d > 0; d >>= 1) { if (tid < d) red[tid] = fmaxf(red[tid], red[tid + d]); __syncthreads(); }
    m = red[0]; __syncthreads();

    float s = 0.f;
    for (int i = tid; i < kend; i += 256) { float e = expf(row[i] - m); buf[i] = e; s += e; }
    red[tid] = s; __syncthreads();
    for (int d = 128; d > 0; d >>= 1) { if (tid < d) red[tid] += red[tid + d]; __syncthreads(); }
    const float inv = 1.0f / red[0];
    for (int i = tid; i < kend; i += 256) row[i] = buf[i] * inv;
}

// ---------------- launch ----------------
extern "C" void kernel_launch(void* const* d_in, const int* in_sizes, int n_in,
                              void* d_out, int out_size)
{
    const float* x     = (const float*)d_in[0];
    const float* W_DQ  = (const float*)d_in[1];
    const float* W_UQ  = (const float*)d_in[2];
    const float* W_QR  = (const float*)d_in[3];
    const float* W_DKV = (const float*)d_in[4];
    const float* W_UK  = (const float*)d_in[5];
    const float* W_UV  = (const float*)d_in[6];
    const float* W_KR  = (const float*)d_in[7];
    const float* W_O   = (const float*)d_in[8];
    const float* qnw   = (const float*)d_in[9];
    const float* kvnw  = (const float*)d_in[10];
    float* out = (float*)d_out;

    float *cQ, *cKV, *q, *k, *v, *kR, *sc, *ao;
    cudaGetSymbolAddress((void**)&cQ,  g_cQ);
    cudaGetSymbolAddress((void**)&cKV, g_cKV);
    cudaGetSymbolAddress((void**)&q,   g_q);
    cudaGetSymbolAddress((void**)&k,   g_k);
    cudaGetSymbolAddress((void**)&v,   g_v);
    cudaGetSymbolAddress((void**)&kR,  g_kR);
    cudaGetSymbolAddress((void**)&sc,  g_sc);
    cudaGetSymbolAddress((void**)&ao,  g_ao);

    const dim3 blk(256);

    // 1) c_Q = x @ W_DQ ; RMSNorm
    bgemm_kernel<<<dim3(DQ/128, NTOK/128, 1), blk>>>(x,0,0, W_DQ,0,0, cQ,0,0,
        1, DD, DQ, DQ, DD, 0, 0, 0);
    rmsnorm_kernel<<<NTOK, blk>>>(cQ, qnw, DQ);

    // 2) c_KV = x @ W_DKV ; RMSNorm
    bgemm_kernel<<<dim3(DKV/128, NTOK/128, 1), blk>>>(x,0,0, W_DKV,0,0, cKV,0,0,
        1, DD, DKV, DKV, DD, 0, 0, 0);
    rmsnorm_kernel<<<NTOK, blk>>>(cKV, kvnw, DKV);

    // 3) q content + rope parts into g_q (B,T,H,192)
    bgemm_kernel<<<dim3((HH*DH)/128, NTOK/128, 1), blk>>>(cQ,0,0, W_UQ,0,0, q,0,0,
        1, DQ, HH*DH, HH*DQK, DQ, DH, 0, 0);
    bgemm_kernel<<<dim3((HH*DR)/128, NTOK/128, 1), blk>>>(cQ,0,0, W_QR,0,0, q,0,0,
        1, DQ, HH*DR, HH*DQK, DQ, DR, DH, 0);

    // 4) k content into g_k ; v into g_v (plain B,T,H*128)
    bgemm_kernel<<<dim3((HH*DH)/128, NTOK/128, 1), blk>>>(cKV,0,0, W_UK,0,0, k,0,0,
        1, DKV, HH*DH, HH*DQK, DKV, DH, 0, 0);
    bgemm_kernel<<<dim3((HH*DH)/128, NTOK/128, 1), blk>>>(cKV,0,0, W_UV,0,0, v,0,0,
        1, DKV, HH*DH, HH*DH, DKV, 0, 0, 0);

    // 5) k_R = x @ W_KR  (N=64, fp32)
    sgemm_kernel<<<dim3(DR/64, NTOK/64), blk>>>(x, W_KR, kR, DD, DR, DR, DD);

    // 6) RoPE
    rope_q_kernel<<<((long)NTOK*HH*32 + 255)/256, blk>>>(q);
    rope_k_kernel<<<((long)NTOK*32 + 255)/256, blk>>>(kR, k);

    // 7) attention: tensor-core scores -> softmax -> tensor-core PV
    scores_mma_kernel<<<dim3(TT/128, TT/128, BHZ), blk>>>(q, k, sc);
    softmax_kernel<<<dim3(TT, BHZ), blk>>>(sc);

    bgemm_kernel<<<dim3(1, TT/128, BHZ), blk>>>(
        sc, (long)HH*TT*TT, (long)TT*TT,
        v,  (long)TT*HH*DH, (long)DH,
        ao, (long)TT*HH*DH, (long)DH,
        HH, TT, HH*DH, HH*DH,
        TT, 0, 0, 1);

    // 8) final: out = ao @ W_O
    bgemm_kernel<<<dim3(DD/128, NTOK/128, 1), blk>>>(ao,0,0, W_O,0,0, out,0,0,
        1, HH*DH, DD, DD, HH*DH, 0, 0, 0);
}